// round 4
// baseline (speedup 1.0000x reference)
#include <cuda_runtime.h>
#include <cstdint>

#define ULL unsigned long long

// Partial projections per (split, z): 12 x 1.5MB.
__device__ float g_p[12][512 * 768];
__device__ float g_ha[512 * 768];
__device__ float g_hb[512 * 768];

__device__ __forceinline__ ULL fma2(ULL a, ULL b, ULL c) {
    ULL d;
    asm("fma.rn.f32x2 %0, %1, %2, %3;" : "=l"(d) : "l"(a), "l"(b), "l"(c));
    return d;
}
__device__ __forceinline__ ULL add2(ULL a, ULL b) {
    ULL d;
    asm("add.rn.f32x2 %0, %1, %2;" : "=l"(d) : "l"(a), "l"(b));
    return d;
}

union F2U { ULL u; float2 f; };
union F4U { float4 f; ULL u[2]; float s[4]; uint4 q; };

__device__ __forceinline__ ULL dupU(float v) {
    F2U d; d.f.x = v; d.f.y = v; return d.u;
}

// ---------------------------------------------------------------------------
// Kernel 1: projection partials, K-split x6.
//   g_p[split*2+z][m][n] = sum_{k in [128*split,128*(split+1))} X[m][k]*W[k][n]
// Block: 256 thr (8 warps). BM=256, BN=64, BK=16. Warp w owns n = n0+8w..+7
// (SHARED across lanes -> W reads broadcast). Lane l owns m-quads l and 32+l
// (m = 4l..4l+3 and 128+4l..+3) -> identity smem layout, conflict-free LDS.128.
// W stored as duplicated (w,w) ULLs -> m-packed FFMA2 with zero dup-MOVs.
// Per k per warp: 2 LDS.128(A, 4cyc ea) + 4 LDS.128(Wdup, bcast 1cyc ea)
//                 + 32 FFMA2  -> crossbar 12 < fma 16 SM-cyc: fma-bound.
// ---------------------------------------------------------------------------
__global__ __launch_bounds__(256, 2) void proj_kernel(
    const float* __restrict__ A,
    const float* __restrict__ Bx,
    const float* __restrict__ W1)
{
    const int z     = blockIdx.z & 1;
    const int split = blockIdx.z >> 1;
    const float* __restrict__ X = z ? Bx : A;
    const float* __restrict__ W = W1 + z * 768 * 768;
    float* __restrict__ out = g_p[blockIdx.z];

    const int m0 = blockIdx.x * 256;   // 2
    const int n0 = blockIdx.y * 64;    // 12
    const int k0 = split * 128;        // 6 splits

    __shared__ uint4 As[2][16][64];    // [buf][k][m-quad]  (identity layout)
    __shared__ ULL   Wd[2][16][64];    // [buf][k][n] duplicated pairs

    const int tid = threadIdx.x;
    const int w = tid >> 5;            // warp 0..7 -> n-block
    const int l = tid & 31;            // lane -> m-quads l, 32+l

    ULL acc[4][8];                     // [m-pair][n]; pairs: q=l:(0,1), q=32+l:(2,3)
#pragma unroll
    for (int i = 0; i < 4; i++)
#pragma unroll
        for (int j = 0; j < 8; j++) acc[i][j] = 0ull;

    // staging coords (kt-invariant)
    const int wk = tid >> 4;           // W: k row 0..15
    const int wn = (tid & 15) * 4;     // W: n offset

    float4 xr[4], wr;

    // ---- prologue: load + store tile 0 ----
#pragma unroll
    for (int j = 0; j < 4; j++)
        xr[j] = *(const float4*)&X[(m0 + tid) * 768 + k0 + 4 * j];
    wr = *(const float4*)&W[(k0 + wk) * 768 + n0 + wn];

#pragma unroll
    for (int j = 0; j < 4; j++) {
        float* dst0 = (float*)&As[0][4 * j + 0][tid >> 2];
        float* dst1 = (float*)&As[0][4 * j + 1][tid >> 2];
        float* dst2 = (float*)&As[0][4 * j + 2][tid >> 2];
        float* dst3 = (float*)&As[0][4 * j + 3][tid >> 2];
        int e = tid & 3;
        dst0[e] = xr[j].x; dst1[e] = xr[j].y; dst2[e] = xr[j].z; dst3[e] = xr[j].w;
    }
    Wd[0][wk][wn + 0] = dupU(wr.x);
    Wd[0][wk][wn + 1] = dupU(wr.y);
    Wd[0][wk][wn + 2] = dupU(wr.z);
    Wd[0][wk][wn + 3] = dupU(wr.w);

    for (int kt = 0; kt < 8; kt++) {
        const int st = kt & 1;
        if (kt < 7) {
            const int kb = k0 + (kt + 1) * 16;
#pragma unroll
            for (int j = 0; j < 4; j++)
                xr[j] = *(const float4*)&X[(m0 + tid) * 768 + kb + 4 * j];
            wr = *(const float4*)&W[(kb + wk) * 768 + n0 + wn];
        }
        __syncthreads();

#pragma unroll
        for (int k = 0; k < 16; k++) {
            F4U a0, a1;
            a0.q = As[st][k][l];
            a1.q = As[st][k][32 + l];
#pragma unroll
            for (int j = 0; j < 4; j++) {
                F4U wv; wv.q = *(const uint4*)&Wd[st][k][8 * w + 2 * j];
                acc[0][2 * j + 0] = fma2(a0.u[0], wv.u[0], acc[0][2 * j + 0]);
                acc[1][2 * j + 0] = fma2(a0.u[1], wv.u[0], acc[1][2 * j + 0]);
                acc[2][2 * j + 0] = fma2(a1.u[0], wv.u[0], acc[2][2 * j + 0]);
                acc[3][2 * j + 0] = fma2(a1.u[1], wv.u[0], acc[3][2 * j + 0]);
                acc[0][2 * j + 1] = fma2(a0.u[0], wv.u[1], acc[0][2 * j + 1]);
                acc[1][2 * j + 1] = fma2(a0.u[1], wv.u[1], acc[1][2 * j + 1]);
                acc[2][2 * j + 1] = fma2(a1.u[0], wv.u[1], acc[2][2 * j + 1]);
                acc[3][2 * j + 1] = fma2(a1.u[1], wv.u[1], acc[3][2 * j + 1]);
            }
        }

        if (kt < 7) {
            const int ns = st ^ 1;
#pragma unroll
            for (int j = 0; j < 4; j++) {
                float* dst0 = (float*)&As[ns][4 * j + 0][tid >> 2];
                float* dst1 = (float*)&As[ns][4 * j + 1][tid >> 2];
                float* dst2 = (float*)&As[ns][4 * j + 2][tid >> 2];
                float* dst3 = (float*)&As[ns][4 * j + 3][tid >> 2];
                int e = tid & 3;
                dst0[e] = xr[j].x; dst1[e] = xr[j].y; dst2[e] = xr[j].z; dst3[e] = xr[j].w;
            }
            Wd[ns][wk][wn + 0] = dupU(wr.x);
            Wd[ns][wk][wn + 1] = dupU(wr.y);
            Wd[ns][wk][wn + 2] = dupU(wr.z);
            Wd[ns][wk][wn + 3] = dupU(wr.w);
        }
    }

    // ---- epilogue: unpack m-pairs, vectorized stores (no bias; reduce adds) ----
#pragma unroll
    for (int q = 0; q < 2; q++) {
        const int mb = m0 + 128 * q + 4 * l;
#pragma unroll
        for (int e = 0; e < 4; e++) {
            const int mp = 2 * q + (e >> 1);
            F2U c[8];
#pragma unroll
            for (int n = 0; n < 8; n++) c[n].u = acc[mp][n];
            float4 v0, v1;
            if (e & 1) {
                v0 = make_float4(c[0].f.y, c[1].f.y, c[2].f.y, c[3].f.y);
                v1 = make_float4(c[4].f.y, c[5].f.y, c[6].f.y, c[7].f.y);
            } else {
                v0 = make_float4(c[0].f.x, c[1].f.x, c[2].f.x, c[3].f.x);
                v1 = make_float4(c[4].f.x, c[5].f.x, c[6].f.x, c[7].f.x);
            }
            *(float4*)&out[(mb + e) * 768 + n0 + 8 * w]     = v0;
            *(float4*)&out[(mb + e) * 768 + n0 + 8 * w + 4] = v1;
        }
    }
}

// ---------------------------------------------------------------------------
// Kernel 1b: reduce 6 K-splits -> g_ha/g_hb, folding b1 into g_ha.
// Pure bandwidth: 19MB read (L2-resident) + 3MB write.
// ---------------------------------------------------------------------------
__global__ __launch_bounds__(256) void reduce_kernel(const float* __restrict__ b1)
{
    const int z = blockIdx.y;
    const int i = blockIdx.x * 256 + threadIdx.x;    // float4 idx, 98304 per z

    float4 r = make_float4(0.f, 0.f, 0.f, 0.f);
#pragma unroll
    for (int sp = 0; sp < 6; sp++) {
        float4 v = *(const float4*)&g_p[(sp << 1) | z][i * 4];
        r.x += v.x; r.y += v.y; r.z += v.z; r.w += v.w;
    }
    if (z == 0) {
        float4 bv = *(const float4*)&b1[(i % 192) * 4];
        r.x += bv.x; r.y += bv.y; r.z += bv.z; r.w += bv.w;
    }
    float* out = z ? g_hb : g_ha;
    *(float4*)&out[i * 4] = r;
}

// ---------------------------------------------------------------------------
// Kernel 2: pairwise relu-reduce (R3 inner loop, 2x blocks for occupancy).
//   scores[b,s,t,o] = sum_h relu(g_ha[b,s,h] + g_hb[b,t,h]) * W2[h,o] + b2[o]
// Grid (4 b, 16 s-tiles of 8, 4 t-tiles of 32) = 256 blocks (2/SM), 4 warps.
// Warp w owns s = s0+2w, s0+2w+1; lane owns t = t0+lane.
// h in 8 chunks of 96, double-buffered, register prefetch, 1 sync/chunk.
// ---------------------------------------------------------------------------
__global__ __launch_bounds__(128) void pair_kernel(
    const float* __restrict__ W2,
    const float* __restrict__ b2,
    float* __restrict__ out)
{
    const int b  = blockIdx.x;
    const int s0 = blockIdx.y * 8;
    const int t0 = blockIdx.z * 32;

    __shared__ __align__(16) float4 haS[2][4][48];  // [buf][warp][hp] (sa,sa',sb,sb')
    __shared__ ULL hbT[2][48][33];                  // [buf][hp][t]
    __shared__ __align__(16) float4 wsS[2][48];     // (w0(h),w0(h+1),w1(h),w1(h+1))

    const int tid  = threadIdx.x;
    const int w    = tid >> 5;    // 0..3
    const int lane = tid & 31;

    // staging coords: ha units (ww,hp): 192 = 128 + 64
    const unsigned e0w = (unsigned)tid / 48u, e0p = (unsigned)tid % 48u;
    const unsigned e1 = (unsigned)tid + 128u;
    const unsigned e1w = e1 / 48u, e1p = e1 % 48u;     // valid iff tid < 64
    // hb units: 32t x 24 f4 = 768 -> 6 per thread
    unsigned tq[6], hq[6];
#pragma unroll
    for (int i = 0; i < 6; i++) {
        unsigned q = (unsigned)tid + 128u * i;
        tq[i] = q / 24u; hq[i] = q % 24u;
    }

    ULL a00 = 0ull, a01 = 0ull, a10 = 0ull, a11 = 0ull;

    float2 pa0[2], pa1[2];
    float4 pb[6];
    float4 pw;

    // ---- LOAD chunk 0 ----
    {
        const int h0 = 0;
        pa0[0] = *(const float2*)&g_ha[(b * 128 + s0 + 2 * e0w) * 768 + h0 + 2 * e0p];
        pa0[1] = *(const float2*)&g_ha[(b * 128 + s0 + 2 * e0w + 1) * 768 + h0 + 2 * e0p];
        if (tid < 64) {
            pa1[0] = *(const float2*)&g_ha[(b * 128 + s0 + 2 * e1w) * 768 + h0 + 2 * e1p];
            pa1[1] = *(const float2*)&g_ha[(b * 128 + s0 + 2 * e1w + 1) * 768 + h0 + 2 * e1p];
        }
#pragma unroll
        for (int i = 0; i < 6; i++)
            pb[i] = *(const float4*)&g_hb[(b * 128 + t0 + tq[i]) * 768 + h0 + hq[i] * 4];
        if (tid < 48) pw = *(const float4*)&W2[(h0 + 2 * tid) * 2];
    }
    // ---- STORE chunk 0 ----
    {
        haS[0][e0w][e0p] = make_float4(pa0[0].x, pa0[0].y, pa0[1].x, pa0[1].y);
        if (tid < 64)
            haS[0][e1w][e1p] = make_float4(pa1[0].x, pa1[0].y, pa1[1].x, pa1[1].y);
#pragma unroll
        for (int i = 0; i < 6; i++) {
            F2U d0; d0.f.x = pb[i].x; d0.f.y = pb[i].y;
            F2U d1; d1.f.x = pb[i].z; d1.f.y = pb[i].w;
            hbT[0][2 * hq[i] + 0][tq[i]] = d0.u;
            hbT[0][2 * hq[i] + 1][tq[i]] = d1.u;
        }
        if (tid < 48) wsS[0][tid] = make_float4(pw.x, pw.z, pw.y, pw.w);
    }

    for (int c = 0; c < 8; c++) {
        const int buf = c & 1;
        if (c < 7) {
            const int h0 = (c + 1) * 96;
            pa0[0] = *(const float2*)&g_ha[(b * 128 + s0 + 2 * e0w) * 768 + h0 + 2 * e0p];
            pa0[1] = *(const float2*)&g_ha[(b * 128 + s0 + 2 * e0w + 1) * 768 + h0 + 2 * e0p];
            if (tid < 64) {
                pa1[0] = *(const float2*)&g_ha[(b * 128 + s0 + 2 * e1w) * 768 + h0 + 2 * e1p];
                pa1[1] = *(const float2*)&g_ha[(b * 128 + s0 + 2 * e1w + 1) * 768 + h0 + 2 * e1p];
            }
#pragma unroll
            for (int i = 0; i < 6; i++)
                pb[i] = *(const float4*)&g_hb[(b * 128 + t0 + tq[i]) * 768 + h0 + hq[i] * 4];
            if (tid < 48) pw = *(const float4*)&W2[(h0 + 2 * tid) * 2];
        }
        __syncthreads();

#pragma unroll 12
        for (int hp = 0; hp < 48; hp++) {
            F4U av; av.f = haS[buf][w][hp];
            ULL vb = hbT[buf][hp][lane];
            F4U wv; wv.f = wsS[buf][hp];

            F2U x0; x0.u = add2(av.u[0], vb);
            x0.f.x = fmaxf(x0.f.x, 0.f);
            x0.f.y = fmaxf(x0.f.y, 0.f);
            F2U x1; x1.u = add2(av.u[1], vb);
            x1.f.x = fmaxf(x1.f.x, 0.f);
            x1.f.y = fmaxf(x1.f.y, 0.f);

            a00 = fma2(x0.u, wv.u[0], a00);
            a01 = fma2(x0.u, wv.u[1], a01);
            a10 = fma2(x1.u, wv.u[0], a10);
            a11 = fma2(x1.u, wv.u[1], a11);
        }

        if (c < 7) {
            const int nb = buf ^ 1;
            haS[nb][e0w][e0p] = make_float4(pa0[0].x, pa0[0].y, pa0[1].x, pa0[1].y);
            if (tid < 64)
                haS[nb][e1w][e1p] = make_float4(pa1[0].x, pa1[0].y, pa1[1].x, pa1[1].y);
#pragma unroll
            for (int i = 0; i < 6; i++) {
                F2U d0; d0.f.x = pb[i].x; d0.f.y = pb[i].y;
                F2U d1; d1.f.x = pb[i].z; d1.f.y = pb[i].w;
                hbT[nb][2 * hq[i] + 0][tq[i]] = d0.u;
                hbT[nb][2 * hq[i] + 1][tq[i]] = d1.u;
            }
            if (tid < 48) wsS[nb][tid] = make_float4(pw.x, pw.z, pw.y, pw.w);
        }
    }

    const float bb0 = b2[0], bb1 = b2[1];
    F2U r00, r01, r10, r11;
    r00.u = a00; r01.u = a01; r10.u = a10; r11.u = a11;

    const int sa = s0 + 2 * w;
    const int t  = t0 + lane;
    float2 oA = make_float2(r00.f.x + r00.f.y + bb0, r01.f.x + r01.f.y + bb1);
    float2 oB = make_float2(r10.f.x + r10.f.y + bb0, r11.f.x + r11.f.y + bb1);
    *(float2*)&out[((b * 128 + sa)     * 128 + t) * 2] = oA;
    *(float2*)&out[((b * 128 + sa + 1) * 128 + t) * 2] = oB;
}

// ---------------------------------------------------------------------------
extern "C" void kernel_launch(void* const* d_in, const int* in_sizes, int n_in,
                              void* d_out, int out_size)
{
    const float* a  = (const float*)d_in[0];   // (4,128,768)
    const float* bx = (const float*)d_in[1];   // (4,128,768)
    const float* W1 = (const float*)d_in[2];   // (1536,768)
    const float* b1 = (const float*)d_in[3];   // (768,)
    const float* W2 = (const float*)d_in[4];   // (768,2)
    const float* b2 = (const float*)d_in[5];   // (2,)
    float* out = (float*)d_out;                // (4,128,128,2)

    proj_kernel<<<dim3(2, 12, 12), 256>>>(a, bx, W1);
    reduce_kernel<<<dim3(384, 2), 256>>>(b1);
    pair_kernel<<<dim3(4, 16, 4), 128>>>(W2, b2, out);
}

// round 6
// speedup vs baseline: 1.6933x; 1.6933x over previous
#include <cuda_runtime.h>
#include <cuda_bf16.h>
#include <cstdint>

#define ULL unsigned long long

// ---------------- global scratch (no allocation) ----------------
__device__ float g_ha[512 * 768];
__device__ float g_hb[512 * 768];
__device__ __nv_bfloat16 g_xhi[2][512 * 768];
__device__ __nv_bfloat16 g_xlo[2][512 * 768];
__device__ __nv_bfloat16 g_whi[2][768 * 768];   // [k][n], natural layout
__device__ __nv_bfloat16 g_wlo[2][768 * 768];

__device__ __forceinline__ ULL fma2(ULL a, ULL b, ULL c) {
    ULL d;
    asm("fma.rn.f32x2 %0, %1, %2, %3;" : "=l"(d) : "l"(a), "l"(b), "l"(c));
    return d;
}
__device__ __forceinline__ ULL add2(ULL a, ULL b) {
    ULL d;
    asm("add.rn.f32x2 %0, %1, %2;" : "=l"(d) : "l"(a), "l"(b));
    return d;
}
union F2U { ULL u; float2 f; };
union F4U { float4 f; ULL u[2]; float s[4]; uint4 q; };
union BQ4 { __nv_bfloat16 h[4]; uint2 q; };

__device__ __forceinline__ uint32_t s2u(const void* p) {
    uint32_t a;
    asm("{ .reg .u64 t; cvta.to.shared.u64 t, %1; cvt.u32.u64 %0, t; }" : "=r"(a) : "l"(p));
    return a;
}
__device__ __forceinline__ void cpa16(const void* smem_dst, const void* gsrc) {
    uint32_t d = s2u(smem_dst);
    asm volatile("cp.async.ca.shared.global [%0], [%1], 16;" :: "r"(d), "l"(gsrc) : "memory");
}
#define CP_COMMIT() asm volatile("cp.async.commit_group;" ::: "memory")
#define CP_WAIT1()  asm volatile("cp.async.wait_group 1;" ::: "memory")

#define LDSM4(r, addr)                                                         \
    asm volatile("ldmatrix.sync.aligned.m8n8.x4.shared.b16 {%0,%1,%2,%3}, [%4];" \
                 : "=r"((r)[0]), "=r"((r)[1]), "=r"((r)[2]), "=r"((r)[3])      \
                 : "r"(addr))
#define LDSM4T(r, addr)                                                        \
    asm volatile("ldmatrix.sync.aligned.m8n8.x4.trans.shared.b16 {%0,%1,%2,%3}, [%4];" \
                 : "=r"((r)[0]), "=r"((r)[1]), "=r"((r)[2]), "=r"((r)[3])      \
                 : "r"(addr))
#define MMA16816(c, a, b)                                                      \
    asm volatile("mma.sync.aligned.m16n8k16.row.col.f32.bf16.bf16.f32 "        \
                 "{%0,%1,%2,%3},{%4,%5,%6,%7},{%8,%9},{%0,%1,%2,%3};"          \
                 : "+f"((c)[0]), "+f"((c)[1]), "+f"((c)[2]), "+f"((c)[3])      \
                 : "r"((a)[0]), "r"((a)[1]), "r"((a)[2]), "r"((a)[3]),         \
                   "r"((b)[0]), "r"((b)[1]))

// ---------------------------------------------------------------------------
// cvt_x: split a,b fp32 -> bf16 hi/lo.  768 blocks x 256 thr, 1 float4 each.
// ---------------------------------------------------------------------------
__global__ __launch_bounds__(256) void cvt_x_kernel(
    const float* __restrict__ A, const float* __restrict__ Bx)
{
    int u = blockIdx.x * 256 + threadIdx.x;      // 0..196607
    int z = u / 98304;
    int r = u - z * 98304;
    const float* X = z ? Bx : A;
    float4 v = *(const float4*)&X[r * 4];
    BQ4 H, L;
    float x;
    x = v.x; H.h[0] = __float2bfloat16(x); L.h[0] = __float2bfloat16(x - __bfloat162float(H.h[0]));
    x = v.y; H.h[1] = __float2bfloat16(x); L.h[1] = __float2bfloat16(x - __bfloat162float(H.h[1]));
    x = v.z; H.h[2] = __float2bfloat16(x); L.h[2] = __float2bfloat16(x - __bfloat162float(H.h[2]));
    x = v.w; H.h[3] = __float2bfloat16(x); L.h[3] = __float2bfloat16(x - __bfloat162float(H.h[3]));
    *(uint2*)&g_xhi[z][r * 4] = H.q;
    *(uint2*)&g_xlo[z][r * 4] = L.q;
}

// ---------------------------------------------------------------------------
// cvt_w: split W1 fp32 -> bf16 hi/lo (same [k][n] layout, no transpose:
// mma .row.col consumes B via ldmatrix.trans of [k][n]).  1152 blocks.
// ---------------------------------------------------------------------------
__global__ __launch_bounds__(256) void cvt_w_kernel(const float* __restrict__ W1)
{
    int u = blockIdx.x * 256 + threadIdx.x;      // 0..294911
    int z = u / 147456;
    int r = u - z * 147456;
    float4 v = *(const float4*)&W1[(z * 147456 + r) * 4];
    BQ4 H, L;
    float x;
    x = v.x; H.h[0] = __float2bfloat16(x); L.h[0] = __float2bfloat16(x - __bfloat162float(H.h[0]));
    x = v.y; H.h[1] = __float2bfloat16(x); L.h[1] = __float2bfloat16(x - __bfloat162float(H.h[1]));
    x = v.z; H.h[2] = __float2bfloat16(x); L.h[2] = __float2bfloat16(x - __bfloat162float(H.h[2]));
    x = v.w; H.h[3] = __float2bfloat16(x); L.h[3] = __float2bfloat16(x - __bfloat162float(H.h[3]));
    *(uint2*)&g_whi[z][r * 4] = H.q;
    *(uint2*)&g_wlo[z][r * 4] = L.q;
}

// ---------------------------------------------------------------------------
// gemm: warp-MMA bf16-split GEMM.  D = X@W (+b1 if z==0), fp32 accum,
// via Xhi@Whi + Xhi@Wlo + Xlo@Whi  (lo*lo dropped, ~2^-18 rel).
// BM=128, BN=32, BK=16. Grid (4 m, 24 n, 2 z) = 192 CTAs, 256 thr (8 warps,
// 4m x 2n; warp tile 32m x 16n). 3-stage cp.async pipeline, 1 sync/chunk.
// Smem pads: A row stride 24 bf16 (48B), B 40 bf16 (80B) -> ldmatrix rows hit
// 8 distinct 16B banks mod 128 (conflict-free).
// ---------------------------------------------------------------------------
__global__ __launch_bounds__(256) void gemm_kernel(const float* __restrict__ b1)
{
    const int z  = blockIdx.z;
    const int m0 = blockIdx.x * 128;
    const int n0 = blockIdx.y * 32;

    __shared__ __nv_bfloat16 As[3][2][128][24];   // [stage][split][m][k16 pad24]
    __shared__ __nv_bfloat16 Bs[3][2][16][40];    // [stage][split][k][n32 pad40]

    const int tid  = threadIdx.x;
    const int lane = tid & 31;
    const int wid  = tid >> 5;
    const int wm   = wid & 3;      // m-quadrant (32 rows)
    const int wn   = wid >> 2;     // n-half (16 cols)

    const __nv_bfloat16* __restrict__ xs[2] = { g_xhi[z], g_xlo[z] };
    const __nv_bfloat16* __restrict__ ws[2] = { g_whi[z], g_wlo[z] };

    float acc[2][2][4];
#pragma unroll
    for (int im = 0; im < 2; im++)
#pragma unroll
        for (int in = 0; in < 2; in++)
#pragma unroll
            for (int r = 0; r < 4; r++) acc[im][in][r] = 0.f;

    // ldmatrix lane addressing (chunk-invariant)
    const int arow = (lane & 7) + 8 * ((lane >> 3) & 1);
    const int akh  = ((lane >> 4) & 1) * 8;
    const int bk   = (lane & 7) + 8 * ((lane >> 3) & 1);
    const int bn   = wn * 16 + ((lane >> 4) & 1) * 8;

    // staging coords (chunk-invariant): A 512 ops = tid, tid+256; B 128 ops
    const int a0sp = 0,            a0row = tid >> 1,          a0h = tid & 1;
    const int a1sp = 1,            a1row = tid >> 1,          a1h = tid & 1;
    const int bsp  = tid >> 6, bkr = (tid >> 2) & 15, bq = tid & 3;

    auto issue = [&](int c, int s) {
        const int k0 = c * 16;
        cpa16(&As[s][a0sp][a0row][a0h * 8], &xs[0][(m0 + a0row) * 768 + k0 + a0h * 8]);
        cpa16(&As[s][a1sp][a1row][a1h * 8], &xs[1][(m0 + a1row) * 768 + k0 + a1h * 8]);
        if (tid < 128)
            cpa16(&Bs[s][bsp][bkr][bq * 8], &ws[bsp][(k0 + bkr) * 768 + n0 + bq * 8]);
    };

    issue(0, 0); CP_COMMIT();
    issue(1, 1); CP_COMMIT();

    for (int c = 0; c < 48; c++) {
        const int s = c % 3;
        CP_WAIT1();
        __syncthreads();

        uint32_t ah[2][4], al[2][4], bh[4], bl[4];
#pragma unroll
        for (int im = 0; im < 2; im++) {
            LDSM4(ah[im], s2u(&As[s][0][wm * 32 + im * 16 + arow][akh]));
            LDSM4(al[im], s2u(&As[s][1][wm * 32 + im * 16 + arow][akh]));
        }
        LDSM4T(bh, s2u(&Bs[s][0][bk][bn]));
        LDSM4T(bl, s2u(&Bs[s][1][bk][bn]));

#pragma unroll
        for (int im = 0; im < 2; im++)
#pragma unroll
            for (int in = 0; in < 2; in++) {
                MMA16816(acc[im][in], ah[im], &bh[in * 2]);
                MMA16816(acc[im][in], ah[im], &bl[in * 2]);
                MMA16816(acc[im][in], al[im], &bh[in * 2]);
            }

        if (c + 2 < 48) issue(c + 2, (c + 2) % 3);
        CP_COMMIT();
    }

    // ---- epilogue ----
    float* __restrict__ outp = z ? g_hb : g_ha;
#pragma unroll
    for (int im = 0; im < 2; im++)
#pragma unroll
        for (int in = 0; in < 2; in++) {
            const int mA = m0 + wm * 32 + im * 16 + (lane >> 2);
            const int nG = n0 + wn * 16 + in * 8 + 2 * (lane & 3);
            float2 v0 = make_float2(acc[im][in][0], acc[im][in][1]);
            float2 v1 = make_float2(acc[im][in][2], acc[im][in][3]);
            if (z == 0) {
                float2 bb = *(const float2*)&b1[nG];
                v0.x += bb.x; v0.y += bb.y;
                v1.x += bb.x; v1.y += bb.y;
            }
            *(float2*)&outp[mA * 768 + nG]       = v0;
            *(float2*)&outp[(mA + 8) * 768 + nG] = v1;
        }
}

// ---------------------------------------------------------------------------
// pair_kernel: R3 version verbatim (measured 16.7us).
// scores[b,s,t,o] = sum_h relu(g_ha[b,s,h]+g_hb[b,t,h])*W2[h,o] + b2[o]
// ---------------------------------------------------------------------------
__global__ __launch_bounds__(256) void pair_kernel(
    const float* __restrict__ W2,
    const float* __restrict__ b2,
    float* __restrict__ out)
{
    const int b  = blockIdx.x;
    const int s0 = blockIdx.y * 16;
    const int t0 = blockIdx.z * 32;

    __shared__ __align__(16) float4 haS[2][8][48];
    __shared__ ULL hbT[2][48][33];
    __shared__ __align__(16) float4 wsS[2][48];

    const int tid  = threadIdx.x;
    const int w    = tid >> 5;
    const int lane = tid & 31;

    const unsigned e0w = (unsigned)tid / 48u, e0p = (unsigned)tid % 48u;
    const unsigned e1 = (unsigned)tid + 256u;
    const unsigned e1w = e1 / 48u, e1p = e1 % 48u;
    unsigned tq[3], hq[3];
#pragma unroll
    for (int i = 0; i < 3; i++) {
        unsigned q = (unsigned)tid + 256u * i;
        tq[i] = q / 24u; hq[i] = q % 24u;
    }

    ULL a00 = 0ull, a01 = 0ull, a10 = 0ull, a11 = 0ull;
    float2 pa0[2], pa1[2];
    float4 pb[3];
    float4 pw;

    {
        const int h0 = 0;
        pa0[0] = *(const float2*)&g_ha[(b * 128 + s0 + 2 * e0w) * 768 + h0 + 2 * e0p];
        pa0[1] = *(const float2*)&g_ha[(b * 128 + s0 + 2 * e0w + 1) * 768 + h0 + 2 * e0p];
        if (tid < 128) {
            pa1[0] = *(const float2*)&g_ha[(b * 128 + s0 + 2 * e1w) * 768 + h0 + 2 * e1p];
            pa1[1] = *(const float2*)&g_ha[(b * 128 + s0 + 2 * e1w + 1) * 768 + h0 + 2 * e1p];
        }
#pragma unroll
        for (int i = 0; i < 3; i++)
            pb[i] = *(const float4*)&g_hb[(b * 128 + t0 + tq[i]) * 768 + h0 + hq[i] * 4];
        if (tid < 48) pw = *(const float4*)&W2[(h0 + 2 * tid) * 2];
    }
    {
        haS[0][e0w][e0p] = make_float4(pa0[0].x, pa0[0].y, pa0[1].x, pa0[1].y);
        if (tid < 128)
            haS[0][e1w][e1p] = make_float4(pa1[0].x, pa1[0].y, pa1[1].x, pa1[1].y);
#pragma unroll
        for (int i = 0; i < 3; i++) {
            F2U d0; d0.f.x = pb[i].x; d0.f.y = pb[i].y;
            F2U d1; d1.f.x = pb[i].z; d1.f.y = pb[i].w;
            hbT[0][2 * hq[i] + 0][tq[i]] = d0.u;
            hbT[0][2 * hq[i] + 1][tq[i]] = d1.u;
        }
        if (tid < 48) wsS[0][tid] = make_float4(pw.x, pw.z, pw.y, pw.w);
    }

    for (int c = 0; c < 8; c++) {
        const int buf = c & 1;
        if (c < 7) {
            const int h0 = (c + 1) * 96;
            pa0[0] = *(const float2*)&g_ha[(b * 128 + s0 + 2 * e0w) * 768 + h0 + 2 * e0p];
            pa0[1] = *(const float2*)&g_ha[(b * 128 + s0 + 2 * e0w + 1) * 768 + h0 + 2 * e0p];
            if (tid < 128) {
                pa1[0] = *(const float2*)&g_ha[(b * 128 + s0 + 2 * e1w) * 768 + h0 + 2 * e1p];
                pa1[1] = *(const float2*)&g_ha[(b * 128 + s0 + 2 * e1w + 1) * 768 + h0 + 2 * e1p];
            }
#pragma unroll
            for (int i = 0; i < 3; i++)
                pb[i] = *(const float4*)&g_hb[(b * 128 + t0 + tq[i]) * 768 + h0 + hq[i] * 4];
            if (tid < 48) pw = *(const float4*)&W2[(h0 + 2 * tid) * 2];
        }
        __syncthreads();

#pragma unroll 12
        for (int hp = 0; hp < 48; hp++) {
            F4U av; av.f = haS[buf][w][hp];
            ULL vb = hbT[buf][hp][lane];
            F4U wv; wv.f = wsS[buf][hp];

            F2U x0; x0.u = add2(av.u[0], vb);
            x0.f.x = fmaxf(x0.f.x, 0.f);
            x0.f.y = fmaxf(x0.f.y, 0.f);
            F2U x1; x1.u = add2(av.u[1], vb);
            x1.f.x = fmaxf(x1.f.x, 0.f);
            x1.f.y = fmaxf(x1.f.y, 0.f);

            a00 = fma2(x0.u, wv.u[0], a00);
            a01 = fma2(x0.u, wv.u[1], a01);
            a10 = fma2(x1.u, wv.u[0], a10);
            a11 = fma2(x1.u, wv.u[1], a11);
        }

        if (c < 7) {
            const int nb = buf ^ 1;
            haS[nb][e0w][e0p] = make_float4(pa0[0].x, pa0[0].y, pa0[1].x, pa0[1].y);
            if (tid < 128)
                haS[nb][e1w][e1p] = make_float4(pa1[0].x, pa1[0].y, pa1[1].x, pa1[1].y);
#pragma unroll
            for (int i = 0; i < 3; i++) {
                F2U d0; d0.f.x = pb[i].x; d0.f.y = pb[i].y;
                F2U d1; d1.f.x = pb[i].z; d1.f.y = pb[i].w;
                hbT[nb][2 * hq[i] + 0][tq[i]] = d0.u;
                hbT[nb][2 * hq[i] + 1][tq[i]] = d1.u;
            }
            if (tid < 48) wsS[nb][tid] = make_float4(pw.x, pw.z, pw.y, pw.w);
        }
    }

    const float bb0 = b2[0], bb1 = b2[1];
    F2U r00, r01, r10, r11;
    r00.u = a00; r01.u = a01; r10.u = a10; r11.u = a11;

    const int sa = s0 + 2 * w;
    const int t  = t0 + lane;
    float2 oA = make_float2(r00.f.x + r00.f.y + bb0, r01.f.x + r01.f.y + bb1);
    float2 oB = make_float2(r10.f.x + r10.f.y + bb0, r11.f.x + r11.f.y + bb1);
    *(float2*)&out[((b * 128 + sa)     * 128 + t) * 2] = oA;
    *(float2*)&out[((b * 128 + sa + 1) * 128 + t) * 2] = oB;
}

// ---------------------------------------------------------------------------
extern "C" void kernel_launch(void* const* d_in, const int* in_sizes, int n_in,
                              void* d_out, int out_size)
{
    const float* a  = (const float*)d_in[0];   // (4,128,768)
    const float* bx = (const float*)d_in[1];   // (4,128,768)
    const float* W1 = (const float*)d_in[2];   // (1536,768)
    const float* b1 = (const float*)d_in[3];   // (768,)
    const float* W2 = (const float*)d_in[4];   // (768,2)
    const float* b2 = (const float*)d_in[5];   // (2,)
    float* out = (float*)d_out;                // (4,128,128,2)

    cvt_x_kernel<<<768, 256>>>(a, bx);
    cvt_w_kernel<<<1152, 256>>>(W1);
    gemm_kernel<<<dim3(4, 24, 2), 256>>>(b1);
    pair_kernel<<<dim3(4, 8, 4), 256>>>(W2, b2, out);
}

// round 7
// speedup vs baseline: 1.9712x; 1.1641x over previous
#include <cuda_runtime.h>
#include <cuda_bf16.h>
#include <cstdint>

#define ULL unsigned long long

// ---------------- global scratch (no allocation) ----------------
__device__ float g_ha[512 * 768];
__device__ float g_hb[512 * 768];
__device__ float g_part[2][4 * 128 * 128 * 2];
__device__ __nv_bfloat16 g_xhi[2][512 * 768];
__device__ __nv_bfloat16 g_xlo[2][512 * 768];
__device__ __nv_bfloat16 g_whi[2][768 * 768];   // [k][n], natural layout
__device__ __nv_bfloat16 g_wlo[2][768 * 768];

__device__ __forceinline__ ULL fma2(ULL a, ULL b, ULL c) {
    ULL d;
    asm("fma.rn.f32x2 %0, %1, %2, %3;" : "=l"(d) : "l"(a), "l"(b), "l"(c));
    return d;
}
__device__ __forceinline__ ULL add2(ULL a, ULL b) {
    ULL d;
    asm("add.rn.f32x2 %0, %1, %2;" : "=l"(d) : "l"(a), "l"(b));
    return d;
}
union F2U { ULL u; float2 f; };
union F4U { float4 f; ULL u[2]; float s[4]; uint4 q; };
union BQ4 { __nv_bfloat16 h[4]; uint2 q; };

__device__ __forceinline__ uint32_t s2u(const void* p) {
    uint32_t a;
    asm("{ .reg .u64 t; cvta.to.shared.u64 t, %1; cvt.u32.u64 %0, t; }" : "=r"(a) : "l"(p));
    return a;
}
__device__ __forceinline__ void cpa16(const void* smem_dst, const void* gsrc) {
    uint32_t d = s2u(smem_dst);
    asm volatile("cp.async.ca.shared.global [%0], [%1], 16;" :: "r"(d), "l"(gsrc) : "memory");
}
#define CP_COMMIT() asm volatile("cp.async.commit_group;" ::: "memory")
#define CP_WAIT2()  asm volatile("cp.async.wait_group 2;" ::: "memory")

#define LDSM4(r, addr)                                                         \
    asm volatile("ldmatrix.sync.aligned.m8n8.x4.shared.b16 {%0,%1,%2,%3}, [%4];" \
                 : "=r"((r)[0]), "=r"((r)[1]), "=r"((r)[2]), "=r"((r)[3])      \
                 : "r"(addr))
#define LDSM4T(r, addr)                                                        \
    asm volatile("ldmatrix.sync.aligned.m8n8.x4.trans.shared.b16 {%0,%1,%2,%3}, [%4];" \
                 : "=r"((r)[0]), "=r"((r)[1]), "=r"((r)[2]), "=r"((r)[3])      \
                 : "r"(addr))
#define MMA16816(c, a, b)                                                      \
    asm volatile("mma.sync.aligned.m16n8k16.row.col.f32.bf16.bf16.f32 "        \
                 "{%0,%1,%2,%3},{%4,%5,%6,%7},{%8,%9},{%0,%1,%2,%3};"          \
                 : "+f"((c)[0]), "+f"((c)[1]), "+f"((c)[2]), "+f"((c)[3])      \
                 : "r"((a)[0]), "r"((a)[1]), "r"((a)[2]), "r"((a)[3]),         \
                   "r"((b)[0]), "r"((b)[1]))

// ---------------------------------------------------------------------------
// cvt: split X (a,b) and W1 fp32 -> bf16 hi/lo in ONE launch.
// 491520 float4 units total (X: 196608, W: 294912). Grid 1920 x 256.
// ---------------------------------------------------------------------------
__global__ __launch_bounds__(256) void cvt_kernel(
    const float* __restrict__ A, const float* __restrict__ Bx,
    const float* __restrict__ W1)
{
    int u = blockIdx.x * 256 + threadIdx.x;
    const float* src;
    __nv_bfloat16 *dh, *dl;
    int r;
    if (u < 196608) {
        int z = u / 98304;
        r = u - z * 98304;
        src = (z ? Bx : A) + r * 4;
        dh = &g_xhi[z][r * 4];
        dl = &g_xlo[z][r * 4];
    } else {
        int w = u - 196608;
        int z = w / 147456;
        r = w - z * 147456;
        src = W1 + (z * 147456 + r) * 4;
        dh = &g_whi[z][r * 4];
        dl = &g_wlo[z][r * 4];
    }
    float4 v = *(const float4*)src;
    BQ4 H, L;
    float x;
    x = v.x; H.h[0] = __float2bfloat16(x); L.h[0] = __float2bfloat16(x - __bfloat162float(H.h[0]));
    x = v.y; H.h[1] = __float2bfloat16(x); L.h[1] = __float2bfloat16(x - __bfloat162float(H.h[1]));
    x = v.z; H.h[2] = __float2bfloat16(x); L.h[2] = __float2bfloat16(x - __bfloat162float(H.h[2]));
    x = v.w; H.h[3] = __float2bfloat16(x); L.h[3] = __float2bfloat16(x - __bfloat162float(H.h[3]));
    *(uint2*)dh = H.q;
    *(uint2*)dl = L.q;
}

// ---------------------------------------------------------------------------
// gemm: warp-MMA bf16-split GEMM.  D = X@W (+b1 if z==0), fp32 accum,
// via Xhi@Whi + Xhi@Wlo + Xlo@Whi.
// BM=64, BN=32, BK=16. Grid (8 m, 24 n, 2 z) = 384 CTAs, 256 thr
// (8 warps: 4m x 2n; warp tile 16m x 16n). 4-stage cp.async pipeline.
// ---------------------------------------------------------------------------
__global__ __launch_bounds__(256) void gemm_kernel(const float* __restrict__ b1)
{
    const int z  = blockIdx.z;
    const int m0 = blockIdx.x * 64;
    const int n0 = blockIdx.y * 32;

    __shared__ __nv_bfloat16 As[4][2][64][24];   // [stage][split][m][k16 pad24]
    __shared__ __nv_bfloat16 Bs[4][2][16][40];   // [stage][split][k][n32 pad40]

    const int tid  = threadIdx.x;
    const int lane = tid & 31;
    const int wid  = tid >> 5;
    const int wm   = wid & 3;      // m 16-row quadrant
    const int wn   = wid >> 2;     // n 16-col half

    const __nv_bfloat16* __restrict__ xs[2] = { g_xhi[z], g_xlo[z] };
    const __nv_bfloat16* __restrict__ ws[2] = { g_whi[z], g_wlo[z] };

    float acc[2][4];
#pragma unroll
    for (int in = 0; in < 2; in++)
#pragma unroll
        for (int r = 0; r < 4; r++) acc[in][r] = 0.f;

    // ldmatrix lane addressing (chunk-invariant)
    const int arow = (lane & 7) + 8 * ((lane >> 3) & 1);
    const int akh  = ((lane >> 4) & 1) * 8;
    const int bk   = (lane & 7) + 8 * ((lane >> 3) & 1);
    const int bn   = wn * 16 + ((lane >> 4) & 1) * 8;

    // staging coords: A 256 cpa16 ops (1/thread), B 128 ops (tid<128)
    const int asp = tid >> 7, amr = (tid >> 1) & 63, ah8 = tid & 1;
    const int bsp = tid >> 6, bkr = (tid >> 2) & 15, bq = tid & 3;

    auto issue = [&](int c, int s) {
        const int k0 = c * 16;
        cpa16(&As[s][asp][amr][ah8 * 8], &xs[asp][(m0 + amr) * 768 + k0 + ah8 * 8]);
        if (tid < 128)
            cpa16(&Bs[s][bsp][bkr][bq * 8], &ws[bsp][(k0 + bkr) * 768 + n0 + bq * 8]);
    };

    issue(0, 0); CP_COMMIT();
    issue(1, 1); CP_COMMIT();
    issue(2, 2); CP_COMMIT();

    for (int c = 0; c < 48; c++) {
        const int s = c & 3;
        CP_WAIT2();
        __syncthreads();

        if (c + 3 < 48) issue(c + 3, (c + 3) & 3);
        CP_COMMIT();

        uint32_t ah[4], al[4], bh[4], bl[4];
        LDSM4(ah, s2u(&As[s][0][wm * 16 + arow][akh]));
        LDSM4(al, s2u(&As[s][1][wm * 16 + arow][akh]));
        LDSM4T(bh, s2u(&Bs[s][0][bk][bn]));
        LDSM4T(bl, s2u(&Bs[s][1][bk][bn]));

#pragma unroll
        for (int in = 0; in < 2; in++) {
            MMA16816(acc[in], ah, &bh[in * 2]);
            MMA16816(acc[in], ah, &bl[in * 2]);
            MMA16816(acc[in], al, &bh[in * 2]);
        }
    }

    // ---- epilogue ----
    float* __restrict__ outp = z ? g_hb : g_ha;
#pragma unroll
    for (int in = 0; in < 2; in++) {
        const int mA = m0 + wm * 16 + (lane >> 2);
        const int nG = n0 + wn * 16 + in * 8 + 2 * (lane & 3);
        float2 v0 = make_float2(acc[in][0], acc[in][1]);
        float2 v1 = make_float2(acc[in][2], acc[in][3]);
        if (z == 0) {
            float2 bb = *(const float2*)&b1[nG];
            v0.x += bb.x; v0.y += bb.y;
            v1.x += bb.x; v1.y += bb.y;
        }
        *(float2*)&outp[mA * 768 + nG]       = v0;
        *(float2*)&outp[(mA + 8) * 768 + nG] = v1;
    }
}

// ---------------------------------------------------------------------------
// pair_kernel: R3 inner loop, h-SPLIT x2 for occupancy (13.8 warps/SM).
// Each block computes partial sum over 384 h (4 chunks of 96) -> g_part[hs].
// Grid (4 b, 8 s-tiles, 8 = t-tile*2 + hs) = 256 blocks, 256 thr.
// ---------------------------------------------------------------------------
__global__ __launch_bounds__(256) void pair_kernel(
    const float* __restrict__ W2)
{
    const int b  = blockIdx.x;
    const int s0 = blockIdx.y * 16;
    const int t0 = (blockIdx.z >> 1) * 32;
    const int hs = blockIdx.z & 1;
    const int hbase = hs * 384;
    float* __restrict__ out = g_part[hs];

    __shared__ __align__(16) float4 haS[2][8][48];
    __shared__ ULL hbT[2][48][33];
    __shared__ __align__(16) float4 wsS[2][48];

    const int tid  = threadIdx.x;
    const int w    = tid >> 5;
    const int lane = tid & 31;

    const unsigned e0w = (unsigned)tid / 48u, e0p = (unsigned)tid % 48u;
    const unsigned e1 = (unsigned)tid + 256u;
    const unsigned e1w = e1 / 48u, e1p = e1 % 48u;
    unsigned tq[3], hq[3];
#pragma unroll
    for (int i = 0; i < 3; i++) {
        unsigned q = (unsigned)tid + 256u * i;
        tq[i] = q / 24u; hq[i] = q % 24u;
    }

    ULL a00 = 0ull, a01 = 0ull, a10 = 0ull, a11 = 0ull;
    float2 pa0[2], pa1[2];
    float4 pb[3];
    float4 pw;

    {
        const int h0 = hbase;
        pa0[0] = *(const float2*)&g_ha[(b * 128 + s0 + 2 * e0w) * 768 + h0 + 2 * e0p];
        pa0[1] = *(const float2*)&g_ha[(b * 128 + s0 + 2 * e0w + 1) * 768 + h0 + 2 * e0p];
        if (tid < 128) {
            pa1[0] = *(const float2*)&g_ha[(b * 128 + s0 + 2 * e1w) * 768 + h0 + 2 * e1p];
            pa1[1] = *(const float2*)&g_ha[(b * 128 + s0 + 2 * e1w + 1) * 768 + h0 + 2 * e1p];
        }
#pragma unroll
        for (int i = 0; i < 3; i++)
            pb[i] = *(const float4*)&g_hb[(b * 128 + t0 + tq[i]) * 768 + h0 + hq[i] * 4];
        if (tid < 48) pw = *(const float4*)&W2[(h0 + 2 * tid) * 2];
    }
    {
        haS[0][e0w][e0p] = make_float4(pa0[0].x, pa0[0].y, pa0[1].x, pa0[1].y);
        if (tid < 128)
            haS[0][e1w][e1p] = make_float4(pa1[0].x, pa1[0].y, pa1[1].x, pa1[1].y);
#pragma unroll
        for (int i = 0; i < 3; i++) {
            F2U d0; d0.f.x = pb[i].x; d0.f.y = pb[i].y;
            F2U d1; d1.f.x = pb[i].z; d1.f.y = pb[i].w;
            hbT[0][2 * hq[i] + 0][tq[i]] = d0.u;
            hbT[0][2 * hq[i] + 1][tq[i]] = d1.u;
        }
        if (tid < 48) wsS[0][tid] = make_float4(pw.x, pw.z, pw.y, pw.w);
    }

    for (int c = 0; c < 4; c++) {
        const int buf = c & 1;
        if (c < 3) {
            const int h0 = hbase + (c + 1) * 96;
            pa0[0] = *(const float2*)&g_ha[(b * 128 + s0 + 2 * e0w) * 768 + h0 + 2 * e0p];
            pa0[1] = *(const float2*)&g_ha[(b * 128 + s0 + 2 * e0w + 1) * 768 + h0 + 2 * e0p];
            if (tid < 128) {
                pa1[0] = *(const float2*)&g_ha[(b * 128 + s0 + 2 * e1w) * 768 + h0 + 2 * e1p];
                pa1[1] = *(const float2*)&g_ha[(b * 128 + s0 + 2 * e1w + 1) * 768 + h0 + 2 * e1p];
            }
#pragma unroll
            for (int i = 0; i < 3; i++)
                pb[i] = *(const float4*)&g_hb[(b * 128 + t0 + tq[i]) * 768 + h0 + hq[i] * 4];
            if (tid < 48) pw = *(const float4*)&W2[(h0 + 2 * tid) * 2];
        }
        __syncthreads();

#pragma unroll 12
        for (int hp = 0; hp < 48; hp++) {
            F4U av; av.f = haS[buf][w][hp];
            ULL vb = hbT[buf][hp][lane];
            F4U wv; wv.f = wsS[buf][hp];

            F2U x0; x0.u = add2(av.u[0], vb);
            x0.f.x = fmaxf(x0.f.x, 0.f);
            x0.f.y = fmaxf(x0.f.y, 0.f);
            F2U x1; x1.u = add2(av.u[1], vb);
            x1.f.x = fmaxf(x1.f.x, 0.f);
            x1.f.y = fmaxf(x1.f.y, 0.f);

            a00 = fma2(x0.u, wv.u[0], a00);
            a01 = fma2(x0.u, wv.u[1], a01);
            a10 = fma2(x1.u, wv.u[0], a10);
            a11 = fma2(x1.u, wv.u[1], a11);
        }

        if (c < 3) {
            const int nb = buf ^ 1;
            haS[nb][e0w][e0p] = make_float4(pa0[0].x, pa0[0].y, pa0[1].x, pa0[1].y);
            if (tid < 128)
                haS[nb][e1w][e1p] = make_float4(pa1[0].x, pa1[0].y, pa1[1].x, pa1[1].y);
#pragma unroll
            for (int i = 0; i < 3; i++) {
                F2U d0; d0.f.x = pb[i].x; d0.f.y = pb[i].y;
                F2U d1; d1.f.x = pb[i].z; d1.f.y = pb[i].w;
                hbT[nb][2 * hq[i] + 0][tq[i]] = d0.u;
                hbT[nb][2 * hq[i] + 1][tq[i]] = d1.u;
            }
            if (tid < 48) wsS[nb][tid] = make_float4(pw.x, pw.z, pw.y, pw.w);
        }
    }

    F2U r00, r01, r10, r11;
    r00.u = a00; r01.u = a01; r10.u = a10; r11.u = a11;

    const int sa = s0 + 2 * w;
    const int t  = t0 + lane;
    float2 oA = make_float2(r00.f.x + r00.f.y, r01.f.x + r01.f.y);
    float2 oB = make_float2(r10.f.x + r10.f.y, r11.f.x + r11.f.y);
    *(float2*)&out[((b * 128 + sa)     * 128 + t) * 2] = oA;
    *(float2*)&out[((b * 128 + sa + 1) * 128 + t) * 2] = oB;
}

// ---------------------------------------------------------------------------
// combine: out = part0 + part1 + b2.  32768 float4 units / 256 = 128 blocks.
// ---------------------------------------------------------------------------
__global__ __launch_bounds__(256) void combine_kernel(
    const float* __restrict__ b2, float* __restrict__ out)
{
    const int i = (blockIdx.x * 256 + threadIdx.x) * 4;
    float4 p0 = *(const float4*)&g_part[0][i];
    float4 p1 = *(const float4*)&g_part[1][i];
    const float b0 = b2[0], b1v = b2[1];
    float4 r = make_float4(p0.x + p1.x + b0, p0.y + p1.y + b1v,
                           p0.z + p1.z + b0, p0.w + p1.w + b1v);
    *(float4*)&out[i] = r;
}

// ---------------------------------------------------------------------------
extern "C" void kernel_launch(void* const* d_in, const int* in_sizes, int n_in,
                              void* d_out, int out_size)
{
    const float* a  = (const float*)d_in[0];   // (4,128,768)
    const float* bx = (const float*)d_in[1];   // (4,128,768)
    const float* W1 = (const float*)d_in[2];   // (1536,768)
    const float* b1 = (const float*)d_in[3];   // (768,)
    const float* W2 = (const float*)d_in[4];   // (768,2)
    const float* b2 = (const float*)d_in[5];   // (2,)
    float* out = (float*)d_out;                // (4,128,128,2)

    cvt_kernel<<<1920, 256>>>(a, bx, W1);
    gemm_kernel<<<dim3(8, 24, 2), 256>>>(b1);
    pair_kernel<<<dim3(4, 8, 8), 256>>>(W2);
    combine_kernel<<<128, 256>>>(b2, out);
}

// round 8
// speedup vs baseline: 2.1488x; 1.0901x over previous
#include <cuda_runtime.h>
#include <cuda_fp16.h>
#include <cstdint>

#define ULL unsigned long long

// ---------------- global scratch (no allocation) ----------------
__device__ float g_ha[512 * 768];
__device__ float g_hb[512 * 768];
__device__ __half g_xh[2][512 * 768];
__device__ __half g_wh[2][768 * 768];   // [k][n], natural layout

__device__ __forceinline__ ULL fma2(ULL a, ULL b, ULL c) {
    ULL d;
    asm("fma.rn.f32x2 %0, %1, %2, %3;" : "=l"(d) : "l"(a), "l"(b), "l"(c));
    return d;
}
__device__ __forceinline__ ULL add2(ULL a, ULL b) {
    ULL d;
    asm("add.rn.f32x2 %0, %1, %2;" : "=l"(d) : "l"(a), "l"(b));
    return d;
}
union F2U { ULL u; float2 f; };
union F4U { float4 f; ULL u[2]; float s[4]; uint4 q; };
union H4U { __half2 h2[2]; uint2 q; };

__device__ __forceinline__ uint32_t s2u(const void* p) {
    uint32_t a;
    asm("{ .reg .u64 t; cvta.to.shared.u64 t, %1; cvt.u32.u64 %0, t; }" : "=r"(a) : "l"(p));
    return a;
}
__device__ __forceinline__ void cpa16(const void* smem_dst, const void* gsrc) {
    uint32_t d = s2u(smem_dst);
    asm volatile("cp.async.ca.shared.global [%0], [%1], 16;" :: "r"(d), "l"(gsrc) : "memory");
}
__device__ __forceinline__ void redadd(float* p, float v) {
    asm volatile("red.global.add.f32 [%0], %1;" :: "l"(p), "f"(v) : "memory");
}
#define CP_COMMIT() asm volatile("cp.async.commit_group;" ::: "memory")
#define CP_WAIT2()  asm volatile("cp.async.wait_group 2;" ::: "memory")

#define LDSM4(r, addr)                                                         \
    asm volatile("ldmatrix.sync.aligned.m8n8.x4.shared.b16 {%0,%1,%2,%3}, [%4];" \
                 : "=r"((r)[0]), "=r"((r)[1]), "=r"((r)[2]), "=r"((r)[3])      \
                 : "r"(addr))
#define LDSM4T(r, addr)                                                        \
    asm volatile("ldmatrix.sync.aligned.m8n8.x4.trans.shared.b16 {%0,%1,%2,%3}, [%4];" \
                 : "=r"((r)[0]), "=r"((r)[1]), "=r"((r)[2]), "=r"((r)[3])      \
                 : "r"(addr))
#define MMA16816(c, a, b)                                                      \
    asm volatile("mma.sync.aligned.m16n8k16.row.col.f32.f16.f16.f32 "          \
                 "{%0,%1,%2,%3},{%4,%5,%6,%7},{%8,%9},{%0,%1,%2,%3};"          \
                 : "+f"((c)[0]), "+f"((c)[1]), "+f"((c)[2]), "+f"((c)[3])      \
                 : "r"((a)[0]), "r"((a)[1]), "r"((a)[2]), "r"((a)[3]),         \
                   "r"((b)[0]), "r"((b)[1]))

// ---------------------------------------------------------------------------
// cvt: fp32 -> fp16 for X (a,b) and W1, AND initialize out to broadcast b2
// (pair_kernel accumulates into out with red.global.add).
// Units (float4): X 196608, W 294912, out-init 32768 -> 524288 / 256 = 2048.
// ---------------------------------------------------------------------------
__global__ __launch_bounds__(256) void cvt_kernel(
    const float* __restrict__ A, const float* __restrict__ Bx,
    const float* __restrict__ W1, const float* __restrict__ b2,
    float* __restrict__ out)
{
    int u = blockIdx.x * 256 + threadIdx.x;
    if (u < 196608) {
        int z = u / 98304;
        int r = u - z * 98304;
        float4 v = *(const float4*)&((z ? Bx : A)[r * 4]);
        H4U h;
        h.h2[0] = __float22half2_rn(make_float2(v.x, v.y));
        h.h2[1] = __float22half2_rn(make_float2(v.z, v.w));
        *(uint2*)&g_xh[z][r * 4] = h.q;
    } else if (u < 491520) {
        int w = u - 196608;
        int z = w / 147456;
        int r = w - z * 147456;
        float4 v = *(const float4*)&W1[(z * 147456 + r) * 4];
        H4U h;
        h.h2[0] = __float22half2_rn(make_float2(v.x, v.y));
        h.h2[1] = __float22half2_rn(make_float2(v.z, v.w));
        *(uint2*)&g_wh[z][r * 4] = h.q;
    } else {
        int i = u - 491520;                    // 0..32767
        float b0 = b2[0], b1v = b2[1];
        *(float4*)&out[i * 4] = make_float4(b0, b1v, b0, b1v);
    }
}

// ---------------------------------------------------------------------------
// gemm: fp16 warp-MMA GEMM.  D = X@W (+b1 if z==0), fp32 accumulate.
// BM=64, BN=32, BK=32 (2 k-steps/chunk), 24 chunks, 4-stage cp.async.
// Grid (8 m, 24 n, 2 z) = 384 CTAs, 256 thr (8 warps: 4m x 2n; 16m x 16n).
// Smem rows padded to 40 halfs (80B): 16 rows hit 8 distinct 16B banks.
// ---------------------------------------------------------------------------
__global__ __launch_bounds__(256) void gemm_kernel(const float* __restrict__ b1)
{
    const int z  = blockIdx.z;
    const int m0 = blockIdx.x * 64;
    const int n0 = blockIdx.y * 32;

    __shared__ __half As[4][64][40];   // [stage][m][k32 pad40]
    __shared__ __half Bs[4][32][40];   // [stage][k][n32 pad40]

    const int tid  = threadIdx.x;
    const int lane = tid & 31;
    const int wid  = tid >> 5;
    const int wm   = wid & 3;      // m 16-row quadrant
    const int wn   = wid >> 2;     // n 16-col half

    const __half* __restrict__ xs = g_xh[z];
    const __half* __restrict__ ws = g_wh[z];

    float acc[2][4];
#pragma unroll
    for (int in = 0; in < 2; in++)
#pragma unroll
        for (int r = 0; r < 4; r++) acc[in][r] = 0.f;

    // ldmatrix lane addressing (chunk-invariant)
    const int arow = (lane & 7) + 8 * ((lane >> 3) & 1);
    const int akh  = ((lane >> 4) & 1) * 8;
    const int bk   = (lane & 7) + 8 * ((lane >> 3) & 1);
    const int bn   = wn * 16 + ((lane >> 4) & 1) * 8;

    // staging coords: A 256 cpa16 ops (1/thread), B 128 (tid<128)
    const int amr = tid >> 2, aq = tid & 3;
    const int bkr = (tid >> 2) & 31, bq = tid & 3;

    auto issue = [&](int c, int s) {
        const int k0 = c * 32;
        cpa16(&As[s][amr][aq * 8], &xs[(m0 + amr) * 768 + k0 + aq * 8]);
        if (tid < 128)
            cpa16(&Bs[s][bkr][bq * 8], &ws[(k0 + bkr) * 768 + n0 + bq * 8]);
    };

    issue(0, 0); CP_COMMIT();
    issue(1, 1); CP_COMMIT();
    issue(2, 2); CP_COMMIT();

    for (int c = 0; c < 24; c++) {
        const int s = c & 3;
        CP_WAIT2();
        __syncthreads();

        if (c + 3 < 24) issue(c + 3, (c + 3) & 3);
        CP_COMMIT();

#pragma unroll
        for (int kk = 0; kk < 2; kk++) {
            uint32_t a_[4], b_[4];
            LDSM4(a_, s2u(&As[s][wm * 16 + arow][kk * 16 + akh]));
            LDSM4T(b_, s2u(&Bs[s][kk * 16 + bk][bn]));
            MMA16816(acc[0], a_, &b_[0]);
            MMA16816(acc[1], a_, &b_[2]);
        }
    }

    // ---- epilogue ----
    float* __restrict__ outp = z ? g_hb : g_ha;
#pragma unroll
    for (int in = 0; in < 2; in++) {
        const int mA = m0 + wm * 16 + (lane >> 2);
        const int nG = n0 + wn * 16 + in * 8 + 2 * (lane & 3);
        float2 v0 = make_float2(acc[in][0], acc[in][1]);
        float2 v1 = make_float2(acc[in][2], acc[in][3]);
        if (z == 0) {
            float2 bb = *(const float2*)&b1[nG];
            v0.x += bb.x; v0.y += bb.y;
            v1.x += bb.x; v1.y += bb.y;
        }
        *(float2*)&outp[mA * 768 + nG]       = v0;
        *(float2*)&outp[(mA + 8) * 768 + nG] = v1;
    }
}

// ---------------------------------------------------------------------------
// pair_kernel: h-split x2; partials accumulated straight into out via
// red.global.add (out pre-initialized to b2 by cvt_kernel).
// Grid (4 b, 8 s-tiles of 16, 8 = t-tile*2 + hs) = 256 blocks, 256 thr.
// ---------------------------------------------------------------------------
__global__ __launch_bounds__(256) void pair_kernel(
    const float* __restrict__ W2, float* __restrict__ out)
{
    const int b  = blockIdx.x;
    const int s0 = blockIdx.y * 16;
    const int t0 = (blockIdx.z >> 1) * 32;
    const int hbase = (blockIdx.z & 1) * 384;

    __shared__ __align__(16) float4 haS[2][8][48];
    __shared__ ULL hbT[2][48][33];
    __shared__ __align__(16) float4 wsS[2][48];

    const int tid  = threadIdx.x;
    const int w    = tid >> 5;
    const int lane = tid & 31;

    const unsigned e0w = (unsigned)tid / 48u, e0p = (unsigned)tid % 48u;
    const unsigned e1 = (unsigned)tid + 256u;
    const unsigned e1w = e1 / 48u, e1p = e1 % 48u;
    unsigned tq[3], hq[3];
#pragma unroll
    for (int i = 0; i < 3; i++) {
        unsigned q = (unsigned)tid + 256u * i;
        tq[i] = q / 24u; hq[i] = q % 24u;
    }

    ULL a00 = 0ull, a01 = 0ull, a10 = 0ull, a11 = 0ull;
    float2 pa0[2], pa1[2];
    float4 pb[3];
    float4 pw;

    {
        const int h0 = hbase;
        pa0[0] = *(const float2*)&g_ha[(b * 128 + s0 + 2 * e0w) * 768 + h0 + 2 * e0p];
        pa0[1] = *(const float2*)&g_ha[(b * 128 + s0 + 2 * e0w + 1) * 768 + h0 + 2 * e0p];
        if (tid < 128) {
            pa1[0] = *(const float2*)&g_ha[(b * 128 + s0 + 2 * e1w) * 768 + h0 + 2 * e1p];
            pa1[1] = *(const float2*)&g_ha[(b * 128 + s0 + 2 * e1w + 1) * 768 + h0 + 2 * e1p];
        }
#pragma unroll
        for (int i = 0; i < 3; i++)
            pb[i] = *(const float4*)&g_hb[(b * 128 + t0 + tq[i]) * 768 + h0 + hq[i] * 4];
        if (tid < 48) pw = *(const float4*)&W2[(h0 + 2 * tid) * 2];
    }
    {
        haS[0][e0w][e0p] = make_float4(pa0[0].x, pa0[0].y, pa0[1].x, pa0[1].y);
        if (tid < 128)
            haS[0][e1w][e1p] = make_float4(pa1[0].x, pa1[0].y, pa1[1].x, pa1[1].y);
#pragma unroll
        for (int i = 0; i < 3; i++) {
            F2U d0; d0.f.x = pb[i].x; d0.f.y = pb[i].y;
            F2U d1; d1.f.x = pb[i].z; d1.f.y = pb[i].w;
            hbT[0][2 * hq[i] + 0][tq[i]] = d0.u;
            hbT[0][2 * hq[i] + 1][tq[i]] = d1.u;
        }
        if (tid < 48) wsS[0][tid] = make_float4(pw.x, pw.z, pw.y, pw.w);
    }

    for (int c = 0; c < 4; c++) {
        const int buf = c & 1;
        if (c < 3) {
            const int h0 = hbase + (c + 1) * 96;
            pa0[0] = *(const float2*)&g_ha[(b * 128 + s0 + 2 * e0w) * 768 + h0 + 2 * e0p];
            pa0[1] = *(const float2*)&g_ha[(b * 128 + s0 + 2 * e0w + 1) * 768 + h0 + 2 * e0p];
            if (tid < 128) {
                pa1[0] = *(const float2*)&g_ha[(b * 128 + s0 + 2 * e1w) * 768 + h0 + 2 * e1p];
                pa1[1] = *(const float2*)&g_ha[(b * 128 + s0 + 2 * e1w + 1) * 768 + h0 + 2 * e1p];
            }
#pragma unroll
            for (int i = 0; i < 3; i++)
                pb[i] = *(const float4*)&g_hb[(b * 128 + t0 + tq[i]) * 768 + h0 + hq[i] * 4];
            if (tid < 48) pw = *(const float4*)&W2[(h0 + 2 * tid) * 2];
        }
        __syncthreads();

#pragma unroll 12
        for (int hp = 0; hp < 48; hp++) {
            F4U av; av.f = haS[buf][w][hp];
            ULL vb = hbT[buf][hp][lane];
            F4U wv; wv.f = wsS[buf][hp];

            F2U x0; x0.u = add2(av.u[0], vb);
            x0.f.x = fmaxf(x0.f.x, 0.f);
            x0.f.y = fmaxf(x0.f.y, 0.f);
            F2U x1; x1.u = add2(av.u[1], vb);
            x1.f.x = fmaxf(x1.f.x, 0.f);
            x1.f.y = fmaxf(x1.f.y, 0.f);

            a00 = fma2(x0.u, wv.u[0], a00);
            a01 = fma2(x0.u, wv.u[1], a01);
            a10 = fma2(x1.u, wv.u[0], a10);
            a11 = fma2(x1.u, wv.u[1], a11);
        }

        if (c < 3) {
            const int nb = buf ^ 1;
            haS[nb][e0w][e0p] = make_float4(pa0[0].x, pa0[0].y, pa0[1].x, pa0[1].y);
            if (tid < 128)
                haS[nb][e1w][e1p] = make_float4(pa1[0].x, pa1[0].y, pa1[1].x, pa1[1].y);
#pragma unroll
            for (int i = 0; i < 3; i++) {
                F2U d0; d0.f.x = pb[i].x; d0.f.y = pb[i].y;
                F2U d1; d1.f.x = pb[i].z; d1.f.y = pb[i].w;
                hbT[nb][2 * hq[i] + 0][tq[i]] = d0.u;
                hbT[nb][2 * hq[i] + 1][tq[i]] = d1.u;
            }
            if (tid < 48) wsS[nb][tid] = make_float4(pw.x, pw.z, pw.y, pw.w);
        }
    }

    F2U r00, r01, r10, r11;
    r00.u = a00; r01.u = a01; r10.u = a10; r11.u = a11;

    const int sa = s0 + 2 * w;
    const int t  = t0 + lane;
    float* pA = &out[((b * 128 + sa)     * 128 + t) * 2];
    float* pB = &out[((b * 128 + sa + 1) * 128 + t) * 2];
    redadd(pA + 0, r00.f.x + r00.f.y);
    redadd(pA + 1, r01.f.x + r01.f.y);
    redadd(pB + 0, r10.f.x + r10.f.y);
    redadd(pB + 1, r11.f.x + r11.f.y);
}

// ---------------------------------------------------------------------------
extern "C" void kernel_launch(void* const* d_in, const int* in_sizes, int n_in,
                              void* d_out, int out_size)
{
    const float* a  = (const float*)d_in[0];   // (4,128,768)
    const float* bx = (const float*)d_in[1];   // (4,128,768)
    const float* W1 = (const float*)d_in[2];   // (1536,768)
    const float* b1 = (const float*)d_in[3];   // (768,)
    const float* W2 = (const float*)d_in[4];   // (768,2)
    const float* b2 = (const float*)d_in[5];   // (2,)
    float* out = (float*)d_out;                // (4,128,128,2)

    cvt_kernel<<<2048, 256>>>(a, bx, W1, b2, out);
    gemm_kernel<<<dim3(8, 24, 2), 256>>>(b1);
    pair_kernel<<<dim3(4, 8, 8), 256>>>(W2, out);
}

// round 9
// speedup vs baseline: 3.1282x; 1.4557x over previous
#include <cuda_runtime.h>
#include <cuda_fp16.h>
#include <cstdint>

#define ULL unsigned long long

// ---------------- global scratch (no allocation) ----------------
__device__ float g_ha[512 * 768];
__device__ float g_hb[512 * 768];
__device__ __half g_xh[2][512 * 768];
__device__ __half g_wh[2][768 * 768];   // [k][n], natural layout

__device__ __forceinline__ ULL fma2(ULL a, ULL b, ULL c) {
    ULL d;
    asm("fma.rn.f32x2 %0, %1, %2, %3;" : "=l"(d) : "l"(a), "l"(b), "l"(c));
    return d;
}
__device__ __forceinline__ ULL add2(ULL a, ULL b) {
    ULL d;
    asm("add.rn.f32x2 %0, %1, %2;" : "=l"(d) : "l"(a), "l"(b));
    return d;
}
union F2U { ULL u; float2 f; };
union F4U { float4 f; ULL u[2]; float s[4]; uint4 q; };
union H4U { __half2 h2[2]; uint2 q; };

__device__ __forceinline__ uint32_t s2u(const void* p) {
    uint32_t a;
    asm("{ .reg .u64 t; cvta.to.shared.u64 t, %1; cvt.u32.u64 %0, t; }" : "=r"(a) : "l"(p));
    return a;
}
__device__ __forceinline__ void cpa16(const void* smem_dst, const void* gsrc) {
    uint32_t d = s2u(smem_dst);
    asm volatile("cp.async.ca.shared.global [%0], [%1], 16;" :: "r"(d), "l"(gsrc) : "memory");
}
__device__ __forceinline__ void redadd(float* p, float v) {
    asm volatile("red.global.add.f32 [%0], %1;" :: "l"(p), "f"(v) : "memory");
}
#define CP_COMMIT() asm volatile("cp.async.commit_group;" ::: "memory")
#define CP_WAIT2()  asm volatile("cp.async.wait_group 2;" ::: "memory")

#define LDSM4(r, addr)                                                         \
    asm volatile("ldmatrix.sync.aligned.m8n8.x4.shared.b16 {%0,%1,%2,%3}, [%4];" \
                 : "=r"((r)[0]), "=r"((r)[1]), "=r"((r)[2]), "=r"((r)[3])      \
                 : "r"(addr))
#define LDSM4T(r, addr)                                                        \
    asm volatile("ldmatrix.sync.aligned.m8n8.x4.trans.shared.b16 {%0,%1,%2,%3}, [%4];" \
                 : "=r"((r)[0]), "=r"((r)[1]), "=r"((r)[2]), "=r"((r)[3])      \
                 : "r"(addr))
#define MMA16816(c, a, b)                                                      \
    asm volatile("mma.sync.aligned.m16n8k16.row.col.f32.f16.f16.f32 "          \
                 "{%0,%1,%2,%3},{%4,%5,%6,%7},{%8,%9},{%0,%1,%2,%3};"          \
                 : "+f"((c)[0]), "+f"((c)[1]), "+f"((c)[2]), "+f"((c)[3])      \
                 : "r"((a)[0]), "r"((a)[1]), "r"((a)[2]), "r"((a)[3]),         \
                   "r"((b)[0]), "r"((b)[1]))

// ---------------------------------------------------------------------------
// cvt: fp32 -> fp16 for X (a,b) and W1, plus out init to broadcast b2.
// Each thread owns TWO independent float4 units (MLP=2).
// Units: X 196608, W 294912, out-init 32768 -> 524288; 1024 blocks x 256.
// ---------------------------------------------------------------------------
__device__ __forceinline__ void cvt_unit_load(int u,
    const float* __restrict__ A, const float* __restrict__ Bx,
    const float* __restrict__ W1, float4& v, __half** dh, float** po)
{
    *dh = nullptr; *po = nullptr;
    if (u < 196608) {
        int z = u / 98304;
        int r = u - z * 98304;
        v = *(const float4*)&((z ? Bx : A)[r * 4]);
        *dh = &g_xh[z][r * 4];
    } else if (u < 491520) {
        int w = u - 196608;
        int z = w / 147456;
        int r = w - z * 147456;
        v = *(const float4*)&W1[(z * 147456 + r) * 4];
        *dh = &g_wh[z][r * 4];
    }
}

__global__ __launch_bounds__(256) void cvt_kernel(
    const float* __restrict__ A, const float* __restrict__ Bx,
    const float* __restrict__ W1, const float* __restrict__ b2,
    float* __restrict__ out)
{
    const int idx = blockIdx.x * 256 + threadIdx.x;      // 0..262143
    const int u0 = idx, u1 = idx + 262144;

    float4 v0, v1;
    __half *dh0, *dh1;
    float *po0, *po1;
    cvt_unit_load(u0, A, Bx, W1, v0, &dh0, &po0);
    cvt_unit_load(u1, A, Bx, W1, v1, &dh1, &po1);

    if (dh0) {
        H4U h;
        h.h2[0] = __float22half2_rn(make_float2(v0.x, v0.y));
        h.h2[1] = __float22half2_rn(make_float2(v0.z, v0.w));
        *(uint2*)dh0 = h.q;
    }
    if (dh1) {
        H4U h;
        h.h2[0] = __float22half2_rn(make_float2(v1.x, v1.y));
        h.h2[1] = __float22half2_rn(make_float2(v1.z, v1.w));
        *(uint2*)dh1 = h.q;
    } else {
        int i = u1 - 491520;                 // 0..32767
        float b0 = b2[0], b1v = b2[1];
        *(float4*)&out[i * 4] = make_float4(b0, b1v, b0, b1v);
    }
}

// ---------------------------------------------------------------------------
// gemm: fp16 warp-MMA GEMM.  D = X@W (+b1 if z==0), fp32 accumulate.
// BM=64, BN=64, BK=32 (2 k-steps/chunk), 24 chunks, 4-stage cp.async.
// Grid (8 m, 12 n, 2 z) = 192 CTAs, 256 thr (8 warps: 4m x 2n; 16m x 32n).
// Pads: A rows 40 halfs (5r+c mod 8 distinct), B rows 72 (9r+c mod 8 distinct).
// ---------------------------------------------------------------------------
__global__ __launch_bounds__(256) void gemm_kernel(const float* __restrict__ b1)
{
    const int z  = blockIdx.z;
    const int m0 = blockIdx.x * 64;
    const int n0 = blockIdx.y * 64;

    __shared__ __half As[4][64][40];   // [stage][m][k32 pad40]
    __shared__ __half Bs[4][32][72];   // [stage][k][n64 pad72]

    const int tid  = threadIdx.x;
    const int lane = tid & 31;
    const int wid  = tid >> 5;
    const int wm   = wid & 3;      // m 16-row quadrant
    const int wn   = wid >> 2;     // n 32-col half

    const __half* __restrict__ xs = g_xh[z];
    const __half* __restrict__ ws = g_wh[z];

    float acc[4][4];
#pragma unroll
    for (int in = 0; in < 4; in++)
#pragma unroll
        for (int r = 0; r < 4; r++) acc[in][r] = 0.f;

    // ldmatrix lane addressing (chunk-invariant)
    const int arow = (lane & 7) + 8 * ((lane >> 3) & 1);
    const int akh  = ((lane >> 4) & 1) * 8;
    const int bk   = (lane & 7) + 8 * ((lane >> 3) & 1);
    const int bn8  = ((lane >> 4) & 1) * 8;

    // staging coords: A 256 cpa16 ops (1/thread), B 256 (1/thread)
    const int amr = tid >> 2, aq = tid & 3;
    const int bkr = tid >> 3, bq = tid & 7;

    auto issue = [&](int c, int s) {
        const int k0 = c * 32;
        cpa16(&As[s][amr][aq * 8], &xs[(m0 + amr) * 768 + k0 + aq * 8]);
        cpa16(&Bs[s][bkr][bq * 8], &ws[(k0 + bkr) * 768 + n0 + bq * 8]);
    };

    issue(0, 0); CP_COMMIT();
    issue(1, 1); CP_COMMIT();
    issue(2, 2); CP_COMMIT();

    for (int c = 0; c < 24; c++) {
        const int s = c & 3;
        CP_WAIT2();
        __syncthreads();

        if (c + 3 < 24) issue(c + 3, (c + 3) & 3);
        CP_COMMIT();

#pragma unroll
        for (int kk = 0; kk < 2; kk++) {
            uint32_t a_[4], b0_[4], b1_[4];
            LDSM4(a_, s2u(&As[s][wm * 16 + arow][kk * 16 + akh]));
            LDSM4T(b0_, s2u(&Bs[s][kk * 16 + bk][wn * 32 + 0  + bn8]));
            LDSM4T(b1_, s2u(&Bs[s][kk * 16 + bk][wn * 32 + 16 + bn8]));
            MMA16816(acc[0], a_, &b0_[0]);
            MMA16816(acc[1], a_, &b0_[2]);
            MMA16816(acc[2], a_, &b1_[0]);
            MMA16816(acc[3], a_, &b1_[2]);
        }
    }

    // ---- epilogue ----
    float* __restrict__ outp = z ? g_hb : g_ha;
#pragma unroll
    for (int in = 0; in < 4; in++) {
        const int mA = m0 + wm * 16 + (lane >> 2);
        const int nG = n0 + wn * 32 + in * 8 + 2 * (lane & 3);
        float2 v0 = make_float2(acc[in][0], acc[in][1]);
        float2 v1 = make_float2(acc[in][2], acc[in][3]);
        if (z == 0) {
            float2 bb = *(const float2*)&b1[nG];
            v0.x += bb.x; v0.y += bb.y;
            v1.x += bb.x; v1.y += bb.y;
        }
        *(float2*)&outp[mA * 768 + nG]       = v0;
        *(float2*)&outp[(mA + 8) * 768 + nG] = v1;
    }
}

// ---------------------------------------------------------------------------
// pair_kernel: h-split x4 (27.7 warps/SM); partials accumulated into out via
// red.global.add (out pre-initialized to b2 by cvt_kernel).
// Grid (4 b, 8 s-tiles of 16, 16 = t-tile*4 + hs) = 512 blocks, 256 thr.
// Each block: 192 h = 2 chunks of 96, double-buffered.
// ---------------------------------------------------------------------------
__global__ __launch_bounds__(256) void pair_kernel(
    const float* __restrict__ W2, float* __restrict__ out)
{
    const int b  = blockIdx.x;
    const int s0 = blockIdx.y * 16;
    const int t0 = (blockIdx.z >> 2) * 32;
    const int hbase = (blockIdx.z & 3) * 192;

    __shared__ __align__(16) float4 haS[2][8][48];
    __shared__ ULL hbT[2][48][33];
    __shared__ __align__(16) float4 wsS[2][48];

    const int tid  = threadIdx.x;
    const int w    = tid >> 5;
    const int lane = tid & 31;

    const unsigned e0w = (unsigned)tid / 48u, e0p = (unsigned)tid % 48u;
    const unsigned e1 = (unsigned)tid + 256u;
    const unsigned e1w = e1 / 48u, e1p = e1 % 48u;
    unsigned tq[3], hq[3];
#pragma unroll
    for (int i = 0; i < 3; i++) {
        unsigned q = (unsigned)tid + 256u * i;
        tq[i] = q / 24u; hq[i] = q % 24u;
    }

    ULL a00 = 0ull, a01 = 0ull, a10 = 0ull, a11 = 0ull;
    float2 pa0[2], pa1[2];
    float4 pb[3];
    float4 pw;

    {
        const int h0 = hbase;
        pa0[0] = *(const float2*)&g_ha[(b * 128 + s0 + 2 * e0w) * 768 + h0 + 2 * e0p];
        pa0[1] = *(const float2*)&g_ha[(b * 128 + s0 + 2 * e0w + 1) * 768 + h0 + 2 * e0p];
        if (tid < 128) {
            pa1[0] = *(const float2*)&g_ha[(b * 128 + s0 + 2 * e1w) * 768 + h0 + 2 * e1p];
            pa1[1] = *(const float2*)&g_ha[(b * 128 + s0 + 2 * e1w + 1) * 768 + h0 + 2 * e1p];
        }
#pragma unroll
        for (int i = 0; i < 3; i++)
            pb[i] = *(const float4*)&g_hb[(b * 128 + t0 + tq[i]) * 768 + h0 + hq[i] * 4];
        if (tid < 48) pw = *(const float4*)&W2[(h0 + 2 * tid) * 2];
    }
    {
        haS[0][e0w][e0p] = make_float4(pa0[0].x, pa0[0].y, pa0[1].x, pa0[1].y);
        if (tid < 128)
            haS[0][e1w][e1p] = make_float4(pa1[0].x, pa1[0].y, pa1[1].x, pa1[1].y);
#pragma unroll
        for (int i = 0; i < 3; i++) {
            F2U d0; d0.f.x = pb[i].x; d0.f.y = pb[i].y;
            F2U d1; d1.f.x = pb[i].z; d1.f.y = pb[i].w;
            hbT[0][2 * hq[i] + 0][tq[i]] = d0.u;
            hbT[0][2 * hq[i] + 1][tq[i]] = d1.u;
        }
        if (tid < 48) wsS[0][tid] = make_float4(pw.x, pw.z, pw.y, pw.w);
    }

    for (int c = 0; c < 2; c++) {
        const int buf = c & 1;
        if (c < 1) {
            const int h0 = hbase + 96;
            pa0[0] = *(const float2*)&g_ha[(b * 128 + s0 + 2 * e0w) * 768 + h0 + 2 * e0p];
            pa0[1] = *(const float2*)&g_ha[(b * 128 + s0 + 2 * e0w + 1) * 768 + h0 + 2 * e0p];
            if (tid < 128) {
                pa1[0] = *(const float2*)&g_ha[(b * 128 + s0 + 2 * e1w) * 768 + h0 + 2 * e1p];
                pa1[1] = *(const float2*)&g_ha[(b * 128 + s0 + 2 * e1w + 1) * 768 + h0 + 2 * e1p];
            }
#pragma unroll
            for (int i = 0; i < 3; i++)
                pb[i] = *(const float4*)&g_hb[(b * 128 + t0 + tq[i]) * 768 + h0 + hq[i] * 4];
            if (tid < 48) pw = *(const float4*)&W2[(h0 + 2 * tid) * 2];
        }
        __syncthreads();

#pragma unroll 12
        for (int hp = 0; hp < 48; hp++) {
            F4U av; av.f = haS[buf][w][hp];
            ULL vb = hbT[buf][hp][lane];
            F4U wv; wv.f = wsS[buf][hp];

            F2U x0; x0.u = add2(av.u[0], vb);
            x0.f.x = fmaxf(x0.f.x, 0.f);
            x0.f.y = fmaxf(x0.f.y, 0.f);
            F2U x1; x1.u = add2(av.u[1], vb);
            x1.f.x = fmaxf(x1.f.x, 0.f);
            x1.f.y = fmaxf(x1.f.y, 0.f);

            a00 = fma2(x0.u, wv.u[0], a00);
            a01 = fma2(x0.u, wv.u[1], a01);
            a10 = fma2(x1.u, wv.u[0], a10);
            a11 = fma2(x1.u, wv.u[1], a11);
        }

        if (c < 1) {
            const int nb = buf ^ 1;
            haS[nb][e0w][e0p] = make_float4(pa0[0].x, pa0[0].y, pa0[1].x, pa0[1].y);
            if (tid < 128)
                haS[nb][e1w][e1p] = make_float4(pa1[0].x, pa1[0].y, pa1[1].x, pa1[1].y);
#pragma unroll
            for (int i = 0; i < 3; i++) {
                F2U d0; d0.f.x = pb[i].x; d0.f.y = pb[i].y;
                F2U d1; d1.f.x = pb[i].z; d1.f.y = pb[i].w;
                hbT[nb][2 * hq[i] + 0][tq[i]] = d0.u;
                hbT[nb][2 * hq[i] + 1][tq[i]] = d1.u;
            }
            if (tid < 48) wsS[nb][tid] = make_float4(pw.x, pw.z, pw.y, pw.w);
        }
    }

    F2U r00, r01, r10, r11;
    r00.u = a00; r01.u = a01; r10.u = a10; r11.u = a11;

    const int sa = s0 + 2 * w;
    const int t  = t0 + lane;
    float* pA = &out[((b * 128 + sa)     * 128 + t) * 2];
    float* pB = &out[((b * 128 + sa + 1) * 128 + t) * 2];
    redadd(pA + 0, r00.f.x + r00.f.y);
    redadd(pA + 1, r01.f.x + r01.f.y);
    redadd(pB + 0, r10.f.x + r10.f.y);
    redadd(pB + 1, r11.f.x + r11.f.y);
}

// ---------------------------------------------------------------------------
extern "C" void kernel_launch(void* const* d_in, const int* in_sizes, int n_in,
                              void* d_out, int out_size)
{
    const float* a  = (const float*)d_in[0];   // (4,128,768)
    const float* bx = (const float*)d_in[1];   // (4,128,768)
    const float* W1 = (const float*)d_in[2];   // (1536,768)
    const float* b1 = (const float*)d_in[3];   // (768,)
    const float* W2 = (const float*)d_in[4];   // (768,2)
    const float* b2 = (const float*)d_in[5];   // (2,)
    float* out = (float*)d_out;                // (4,128,128,2)

    cvt_kernel<<<1024, 256>>>(a, bx, W1, b2, out);
    gemm_kernel<<<dim3(8, 12, 2), 256>>>(b1);
    pair_kernel<<<dim3(4, 8, 16), 256>>>(W2, out);
}